// round 12
// baseline (speedup 1.0000x reference)
#include <cuda_runtime.h>
#include <math.h>

#define N_BOX 256
#define M_PTS 512
#define KQ    64                  // k-pairs per block (128 m-points)
#define NBLK  (N_BOX * 2 * 4)     // 2048: boxes x 2 j-halves x 4 k-quarters

// c2 = log2(e) / (2 * THETA2^2), THETA2 = 400
#define C2  (1.44269504088896340736f / 320000.0f)
#define L2E 1.44269504088896340736f

__device__ float g_partials[NBLK];
__device__ unsigned int g_count = 0u;   // reset by last block each run

typedef unsigned long long ull;

__device__ __forceinline__ ull pk(float lo, float hi) {
    ull r; asm("mov.b64 %0, {%1, %2};" : "=l"(r) : "f"(lo), "f"(hi)); return r;
}
__device__ __forceinline__ void upk(float& lo, float& hi, ull v) {
    asm("mov.b64 {%0, %1}, %2;" : "=f"(lo), "=f"(hi) : "l"(v));
}
__device__ __forceinline__ ull fma2(ull a, ull b, ull c) {
    ull d; asm("fma.rn.f32x2 %0, %1, %2, %3;" : "=l"(d) : "l"(a), "l"(b), "l"(c)); return d;
}
__device__ __forceinline__ float ex2s(float x) {
    float y; asm("ex2.approx.f32 %0, %1;" : "=f"(y) : "f"(x)); return y;
}

struct PrepOut {
    float mx, my, P, u, v;   // k-side
    float Gx, Gy, gx, gy;    // j-side
};

// ---------------------------------------------------------------------------
// Fully fused kernel. Block = (box i, j-half, k-quarter); 128 threads.
// Phase 1: inline prep (1 k-side + 2 j-side m-points per thread).
// Phase 2: 2 j's/thread over 64 k-pairs. Scalar FFMA t-chains feed ex2
// directly (no pack/unpack movs); accumulation stays packed (fma2) with
// operand pairs coming straight from vector loads. Single-instruction asm
// only, so ptxas schedules the whole loop.
// Phase 3: deterministic block + grid reduction via completion counter.
// ---------------------------------------------------------------------------
__global__ void __launch_bounds__(128, 8) fused_kernel(
    const float* __restrict__ pred,
    const float* __restrict__ target,
    const float* __restrict__ mask,
    const float* __restrict__ grad_x,
    const float* __restrict__ grad_y,
    const float* __restrict__ offset,
    float* __restrict__ out)
{
    __shared__ __align__(16) ull sK[KQ * 6];   // 48B per k-pair, interleaved
    __shared__ float sWarp[4];
    __shared__ int   sLast;

    const int b   = blockIdx.x;
    const int i   = b >> 3;
    const int jc  = (b >> 2) & 1;
    const int kc  = b & 3;
    const int tid = threadIdx.x;

    // ---- per-box scalars (uniform within block; broadcast loads) ----
    const float off0 = offset[2 * i], off1 = offset[2 * i + 1];
    const float px = pred[5 * i]     - off0;
    const float py = pred[5 * i + 1] - off1;
    const float pw = pred[5 * i + 2];
    const float ph = pred[5 * i + 3];
    const float pa = pred[5 * i + 4];
    const float gxc = target[5 * i]     - off0;
    const float gyc = target[5 * i + 1] - off1;
    const float gw  = target[5 * i + 2];
    const float gh  = target[5 * i + 3];
    const float ga  = target[5 * i + 4];

    float cga, sga;  sincosf(ga, &sga, &cga);
    float cpa, spa;  sincosf(pa, &spa, &cpa);
    const float inv_gw = 1.0f / gw;
    const float inv_gh = 1.0f / gh;

    // ---- inline prep for one m-point ----
    auto prep = [&](int m) -> PrepOut {
        const int idx = i * M_PTS + m;
        const float2 mm = ((const float2*)mask)[idx];
        const float mx = mm.x, my = mm.y;

        const float dx = mx - gxc, dy = my - gyc;
        const float r2  = dx * dx + dy * dy;
        const float rin = rsqrtf(fmaxf(r2, 1e-30f));
        const float d   = r2 * rin;
        float arg = -dx * rin;                       // cos(acosv)
        arg = fminf(1.0f, fmaxf(-1.0f, arg));
        const float st = fabsf(dy) * rin;            // sin(acosv)
        const bool  spos = (gyc >= my);              // beta = ga + s*acosv
        const float s = spos ? 1.0f : -1.0f;

        const float cb = cga * arg - s * (sga * st); // cos(beta)
        const float sb = sga * arg + s * (cga * st); // sin(beta)

        const float d_w = fabsf(d * cb);
        const float d_h = fabsf(d * sb);

        const float e1 = ex2s(L2E * 15.0f * (d_w - gw) * inv_gw);
        const float e2 = ex2s(L2E * 15.0f * (d_h - gh) * inv_gh);
        const float a1 = 1.0f / ((1.0f + e1) * (1.0f + e2));

        const float dwp = pw * d_w * inv_gw;
        const float dhp = ph * d_h * inv_gh;
        const float wx =  dwp * cpa, wy = dwp * spa;
        const float hx = -dhp * spa, hy = dhp * cpa;

        bool q2, q3, q4;
        if (spos) {
            q2 = (ga <= 0.0f) && (arg >= cga);
            q3 = false;
            q4 = (arg < sga) && ((ga <= 0.0f) || (arg >= -cga));
        } else {
            q2 = (arg > -sga) && ((ga <= 0.0f) || (arg <= cga));
            q3 = (arg <= -sga) && ((ga >= 0.0f) || (arg > -cga));
            q4 = false;
        }

        float gpx, gpy;
        if (q2)      { gpx =  wx - hx;  gpy =  wy - hy; }
        else if (q3) { gpx =  wx + hx;  gpy =  wy + hy; }
        else if (q4) { gpx = -wx + hx;  gpy = -wy + hy; }
        else         { gpx = -wx - hx;  gpy = -wy - hy; }

        const float gxv = grad_x[idx];
        const float gyv = grad_y[idx];

        PrepOut o;
        o.mx = mx; o.my = my;
        o.P  = C2 * (mx * mx + my * my);
        o.u  = a1 * gxv;
        o.v  = a1 * gyv;
        o.Gx = px + gpx; o.Gy = py + gpy;
        o.gx = gxv; o.gy = gyv;
        return o;
    };

    // ---- phase 1a: k-side (1 point/thread; slot = tid>>1, half = tid&1) ----
    {
        const int m = kc * 128 + tid;      // this k-quarter's m-points
        const PrepOut k0 = prep(m);
        float* f = (float*)&sK[(tid >> 1) * 6];
        const int o = tid & 1;
        f[o]     = k0.mx;
        f[2 + o] = k0.my;
        f[4 + o] = k0.P;
        f[6 + o] = k0.u;
        f[8 + o] = k0.v;
    }

    // ---- phase 1b: j-side (own j's: jc*256 + tid, +128) ----
    const PrepOut J0 = prep(jc * 256 + tid);
    const PrepOut J1 = prep(jc * 256 + tid + 128);
    __syncthreads();

    const float na0 = -2.0f * C2 * J0.Gx;
    const float nb0 = -2.0f * C2 * J0.Gy;
    const float na1 = -2.0f * C2 * J1.Gx;
    const float nb1 = -2.0f * C2 * J1.Gy;
    const float twoQ0 = ex2s(C2 * (J0.Gx * J0.Gx + J0.Gy * J0.Gy));
    const float twoQ1 = ex2s(C2 * (J1.Gx * J1.Gx + J1.Gy * J1.Gy));

    // ---- phase 2: core loop (scalar t -> ex2 -> packed acc) ----
    ull A0 = 0, B0 = 0, A1 = 0, B1 = 0;
    const float* f = (const float*)sK;

#pragma unroll 8
    for (int k2 = 0; k2 < KQ; ++k2, f += 12) {
        const float4 xy = *(const float4*)(f);      // mx0,mx1,my0,my1
        const float4 pu = *(const float4*)(f + 4);  // P0,P1,u0,u1
        const float2 vv = *(const float2*)(f + 8);  // v0,v1

        const ull u2 = pk(pu.z, pu.w);   // pair-aligned: elides to reg pair
        const ull v2 = pk(vv.x, vv.y);

        // j0: scalar t chains feed ex2 directly
        float t0l = fmaf(na0, xy.x, pu.x);
        t0l = fmaf(nb0, xy.z, t0l);
        float t0h = fmaf(na0, xy.y, pu.y);
        t0h = fmaf(nb0, xy.w, t0h);
        const ull e0 = pk(ex2s(t0l), ex2s(t0h));
        A0 = fma2(e0, u2, A0);
        B0 = fma2(e0, v2, B0);

        // j1
        float t1l = fmaf(na1, xy.x, pu.x);
        t1l = fmaf(nb1, xy.z, t1l);
        float t1h = fmaf(na1, xy.y, pu.y);
        t1h = fmaf(nb1, xy.w, t1h);
        const ull e1 = pk(ex2s(t1l), ex2s(t1h));
        A1 = fma2(e1, u2, A1);
        B1 = fma2(e1, v2, B1);
    }

    float al, ah, bl, bh;
    upk(al, ah, A0); upk(bl, bh, B0);
    float partial = (J0.gx * (al + ah) + J0.gy * (bl + bh)) * twoQ0;
    upk(al, ah, A1); upk(bl, bh, B1);
    partial += (J1.gx * (al + ah) + J1.gy * (bl + bh)) * twoQ1;

    // ---- phase 3: deterministic block reduction (4 warps) ----
#pragma unroll
    for (int o = 16; o > 0; o >>= 1)
        partial += __shfl_down_sync(0xffffffffu, partial, o);
    if ((tid & 31) == 0) sWarp[tid >> 5] = partial;
    __syncthreads();

    if (tid == 0) {
        g_partials[b] = sWarp[0] + sWarp[1] + sWarp[2] + sWarp[3];
        __threadfence();
        unsigned int old = atomicAdd(&g_count, 1u);
        sLast = (old == NBLK - 1) ? 1 : 0;
    }
    __syncthreads();

    // last block: fixed-order final reduction, then reset counter
    if (sLast) {
        float s = 0.0f;
#pragma unroll
        for (int r = 0; r < NBLK / 128; ++r)
            s += __ldcg(&g_partials[tid + r * 128]);
#pragma unroll
        for (int o = 16; o > 0; o >>= 1)
            s += __shfl_down_sync(0xffffffffu, s, o);
        if ((tid & 31) == 0) sWarp[tid >> 5] = s;
        __syncthreads();
        if (tid == 0) {
            float v = sWarp[0] + sWarp[1] + sWarp[2] + sWarp[3];
            const double scale = 1.0 / ((double)N_BOX * (double)M_PTS * (double)M_PTS *
                                        2.0 * 3.14159265358979323846 * 400.0);
            *out = (float)((double)v * scale);
            g_count = 0u;   // ready for next graph replay
        }
    }
}

// ---------------------------------------------------------------------------
extern "C" void kernel_launch(void* const* d_in, const int* in_sizes, int n_in,
                              void* d_out, int out_size)
{
    const float* pred    = (const float*)d_in[0];
    const float* target  = (const float*)d_in[1];
    const float* mask    = (const float*)d_in[2];
    const float* grad_x  = (const float*)d_in[3];
    const float* grad_y  = (const float*)d_in[4];
    const float* offset  = (const float*)d_in[5];
    float* out = (float*)d_out;

    fused_kernel<<<NBLK, 128>>>(pred, target, mask, grad_x, grad_y, offset, out);
}

// round 13
// speedup vs baseline: 1.0012x; 1.0012x over previous
#include <cuda_runtime.h>
#include <math.h>

#define N_BOX 256
#define M_PTS 512
#define KHALF 128                 // k-pairs per block (256 m-points)
#define NBLK  (N_BOX * 2 * 2)     // 1024: boxes x 2 j-halves x 2 k-halves

// c2 = log2(e) / (2 * THETA2^2), THETA2 = 400
#define C2  (1.44269504088896340736f / 320000.0f)
#define L2E 1.44269504088896340736f

__device__ float g_partials[NBLK];
__device__ unsigned int g_count = 0u;   // reset by last block each run

typedef unsigned long long ull;

__device__ __forceinline__ ull pk(float lo, float hi) {
    ull r; asm("mov.b64 %0, {%1, %2};" : "=l"(r) : "f"(lo), "f"(hi)); return r;
}
__device__ __forceinline__ void upk(float& lo, float& hi, ull v) {
    asm("mov.b64 {%0, %1}, %2;" : "=f"(lo), "=f"(hi) : "l"(v));
}
__device__ __forceinline__ ull fma2(ull a, ull b, ull c) {
    ull d; asm("fma.rn.f32x2 %0, %1, %2, %3;" : "=l"(d) : "l"(a), "l"(b), "l"(c)); return d;
}
__device__ __forceinline__ float ex2s(float x) {
    float y; asm("ex2.approx.f32 %0, %1;" : "=f"(y) : "f"(x)); return y;
}

struct PrepOut {
    float mx, my, P, u, v;   // k-side
    float Gx, Gy, gx, gy;    // j-side
};

// ---------------------------------------------------------------------------
// Fully fused kernel. Block = (box i, j-half, k-half); 128 threads.
// Phase 1 (inline prep): each thread preps 2 k-side m-points (one full 48B
// smem pair slot) and its 2 j-side m-points (registers).
// Phase 2: 2 j's/thread over 128 k-pairs. Scalar FFMA t-chains feed ex2
// directly; accumulation packed (fma.rn.f32x2). Single-instruction asm only.
// Phase 3: deterministic block + grid reduction via completion counter.
// ---------------------------------------------------------------------------
__global__ void __launch_bounds__(128, 7) fused_kernel(
    const float* __restrict__ pred,
    const float* __restrict__ target,
    const float* __restrict__ mask,
    const float* __restrict__ grad_x,
    const float* __restrict__ grad_y,
    const float* __restrict__ offset,
    float* __restrict__ out)
{
    __shared__ __align__(16) ull sK[KHALF * 6];  // 48B per k-pair, interleaved
    __shared__ float sWarp[4];
    __shared__ int   sLast;

    const int b   = blockIdx.x;
    const int i   = b >> 2;
    const int jc  = (b >> 1) & 1;
    const int kc  = b & 1;
    const int tid = threadIdx.x;

    // ---- per-box scalars (uniform within block; broadcast loads) ----
    const float off0 = offset[2 * i], off1 = offset[2 * i + 1];
    const float px = pred[5 * i]     - off0;
    const float py = pred[5 * i + 1] - off1;
    const float pw = pred[5 * i + 2];
    const float ph = pred[5 * i + 3];
    const float pa = pred[5 * i + 4];
    const float gxc = target[5 * i]     - off0;
    const float gyc = target[5 * i + 1] - off1;
    const float gw  = target[5 * i + 2];
    const float gh  = target[5 * i + 3];
    const float ga  = target[5 * i + 4];

    float cga, sga;  sincosf(ga, &sga, &cga);
    float cpa, spa;  sincosf(pa, &spa, &cpa);
    const float inv_gw = 1.0f / gw;
    const float inv_gh = 1.0f / gh;

    // ---- inline prep for one m-point ----
    auto prep = [&](int m) -> PrepOut {
        const int idx = i * M_PTS + m;
        const float2 mm = ((const float2*)mask)[idx];
        const float mx = mm.x, my = mm.y;

        const float dx = mx - gxc, dy = my - gyc;
        const float r2  = dx * dx + dy * dy;
        const float rin = rsqrtf(fmaxf(r2, 1e-30f));
        const float d   = r2 * rin;
        float arg = -dx * rin;                       // cos(acosv)
        arg = fminf(1.0f, fmaxf(-1.0f, arg));
        const float st = fabsf(dy) * rin;            // sin(acosv)
        const bool  spos = (gyc >= my);              // beta = ga + s*acosv
        const float s = spos ? 1.0f : -1.0f;

        const float cb = cga * arg - s * (sga * st); // cos(beta)
        const float sb = sga * arg + s * (cga * st); // sin(beta)

        const float d_w = fabsf(d * cb);
        const float d_h = fabsf(d * sb);

        const float e1 = ex2s(L2E * 15.0f * (d_w - gw) * inv_gw);
        const float e2 = ex2s(L2E * 15.0f * (d_h - gh) * inv_gh);
        const float a1 = 1.0f / ((1.0f + e1) * (1.0f + e2));

        const float dwp = pw * d_w * inv_gw;
        const float dhp = ph * d_h * inv_gh;
        const float wx =  dwp * cpa, wy = dwp * spa;
        const float hx = -dhp * spa, hy = dhp * cpa;

        bool q2, q3, q4;
        if (spos) {
            q2 = (ga <= 0.0f) && (arg >= cga);
            q3 = false;
            q4 = (arg < sga) && ((ga <= 0.0f) || (arg >= -cga));
        } else {
            q2 = (arg > -sga) && ((ga <= 0.0f) || (arg <= cga));
            q3 = (arg <= -sga) && ((ga >= 0.0f) || (arg > -cga));
            q4 = false;
        }

        float gpx, gpy;
        if (q2)      { gpx =  wx - hx;  gpy =  wy - hy; }
        else if (q3) { gpx =  wx + hx;  gpy =  wy + hy; }
        else if (q4) { gpx = -wx + hx;  gpy = -wy + hy; }
        else         { gpx = -wx - hx;  gpy = -wy - hy; }

        const float gxv = grad_x[idx];
        const float gyv = grad_y[idx];

        PrepOut o;
        o.mx = mx; o.my = my;
        o.P  = C2 * (mx * mx + my * my);
        o.u  = a1 * gxv;
        o.v  = a1 * gyv;
        o.Gx = px + gpx; o.Gy = py + gpy;
        o.gx = gxv; o.gy = gyv;
        return o;
    };

    // ---- phase 1a: k-side (pair slot tid, m = kc*256 + 2tid, +1) ----
    {
        const int m0 = kc * 256 + 2 * tid;
        const PrepOut k0 = prep(m0);
        const PrepOut k1 = prep(m0 + 1);
        ull* dst = &sK[tid * 6];
        ((float4*)dst)[0] = make_float4(k0.mx, k1.mx, k0.my, k1.my);
        ((float4*)dst)[1] = make_float4(k0.P,  k1.P,  k0.u,  k1.u);
        ((float2*)dst)[4] = make_float2(k0.v,  k1.v);
    }

    // ---- phase 1b: j-side (own j's: jc*256 + tid, +128) ----
    const PrepOut J0 = prep(jc * 256 + tid);
    const PrepOut J1 = prep(jc * 256 + tid + 128);
    __syncthreads();

    const float na0 = -2.0f * C2 * J0.Gx;
    const float nb0 = -2.0f * C2 * J0.Gy;
    const float na1 = -2.0f * C2 * J1.Gx;
    const float nb1 = -2.0f * C2 * J1.Gy;
    const float twoQ0 = ex2s(C2 * (J0.Gx * J0.Gx + J0.Gy * J0.Gy));
    const float twoQ1 = ex2s(C2 * (J1.Gx * J1.Gx + J1.Gy * J1.Gy));

    // ---- phase 2: core loop (scalar t -> ex2 -> packed acc) ----
    ull A0 = 0, B0 = 0, A1 = 0, B1 = 0;
    const float* f = (const float*)sK;

#pragma unroll 8
    for (int k2 = 0; k2 < KHALF; ++k2, f += 12) {
        const float4 xy = *(const float4*)(f);      // mx0,mx1,my0,my1
        const float4 pu = *(const float4*)(f + 4);  // P0,P1,u0,u1
        const float2 vv = *(const float2*)(f + 8);  // v0,v1

        const ull u2 = pk(pu.z, pu.w);   // adjacent float4 regs -> pair
        const ull v2 = pk(vv.x, vv.y);

        // j0: scalar t chains feed ex2 directly
        float t0l = fmaf(na0, xy.x, pu.x);
        t0l = fmaf(nb0, xy.z, t0l);
        float t0h = fmaf(na0, xy.y, pu.y);
        t0h = fmaf(nb0, xy.w, t0h);
        const ull e0 = pk(ex2s(t0l), ex2s(t0h));
        A0 = fma2(e0, u2, A0);
        B0 = fma2(e0, v2, B0);

        // j1
        float t1l = fmaf(na1, xy.x, pu.x);
        t1l = fmaf(nb1, xy.z, t1l);
        float t1h = fmaf(na1, xy.y, pu.y);
        t1h = fmaf(nb1, xy.w, t1h);
        const ull e1 = pk(ex2s(t1l), ex2s(t1h));
        A1 = fma2(e1, u2, A1);
        B1 = fma2(e1, v2, B1);
    }

    float al, ah, bl, bh;
    upk(al, ah, A0); upk(bl, bh, B0);
    float partial = (J0.gx * (al + ah) + J0.gy * (bl + bh)) * twoQ0;
    upk(al, ah, A1); upk(bl, bh, B1);
    partial += (J1.gx * (al + ah) + J1.gy * (bl + bh)) * twoQ1;

    // ---- phase 3: deterministic block reduction (4 warps) ----
#pragma unroll
    for (int o = 16; o > 0; o >>= 1)
        partial += __shfl_down_sync(0xffffffffu, partial, o);
    if ((tid & 31) == 0) sWarp[tid >> 5] = partial;
    __syncthreads();

    if (tid == 0) {
        g_partials[b] = sWarp[0] + sWarp[1] + sWarp[2] + sWarp[3];
        __threadfence();
        unsigned int old = atomicAdd(&g_count, 1u);
        sLast = (old == NBLK - 1) ? 1 : 0;
    }
    __syncthreads();

    // last block: fixed-order final reduction (deterministic regardless of
    // which block executes it), then reset the counter for the next replay.
    if (sLast) {
        float s = 0.0f;
#pragma unroll
        for (int r = 0; r < NBLK / 128; ++r)
            s += __ldcg(&g_partials[tid + r * 128]);
#pragma unroll
        for (int o = 16; o > 0; o >>= 1)
            s += __shfl_down_sync(0xffffffffu, s, o);
        if ((tid & 31) == 0) sWarp[tid >> 5] = s;
        __syncthreads();
        if (tid == 0) {
            float v = sWarp[0] + sWarp[1] + sWarp[2] + sWarp[3];
            const double scale = 1.0 / ((double)N_BOX * (double)M_PTS * (double)M_PTS *
                                        2.0 * 3.14159265358979323846 * 400.0);
            *out = (float)((double)v * scale);
            g_count = 0u;   // ready for next graph replay
        }
    }
}

// ---------------------------------------------------------------------------
extern "C" void kernel_launch(void* const* d_in, const int* in_sizes, int n_in,
                              void* d_out, int out_size)
{
    const float* pred    = (const float*)d_in[0];
    const float* target  = (const float*)d_in[1];
    const float* mask    = (const float*)d_in[2];
    const float* grad_x  = (const float*)d_in[3];
    const float* grad_y  = (const float*)d_in[4];
    const float* offset  = (const float*)d_in[5];
    float* out = (float*)d_out;

    fused_kernel<<<NBLK, 128>>>(pred, target, mask, grad_x, grad_y, offset, out);
}